// round 15
// baseline (speedup 1.0000x reference)
#include <cuda_runtime.h>
#include <cuda_bf16.h>
#include <math.h>
#include <stdint.h>

#define BATCH 8
#define SEQ   2048
#define DIM   512
#define SCALE 0.044194173824159216f   /* 1/sqrt(512) */
#define NEGBIG -1e30f

typedef __nv_bfloat16 bf16;

// ---------------- scratch (static device globals; no allocs) ----------------
__device__ __align__(256) float g_pe[SEQ * DIM];
__device__ __align__(256) float g_rk[SEQ * DIM];
__device__ __align__(256) float g_k [BATCH * SEQ * DIM];
__device__ __align__(256) float g_ck[BATCH * SEQ];
__device__ __align__(256) float g_rrel[SEQ];
__device__ __align__(256) float g_S[(size_t)BATCH * SEQ * SEQ];
// bf16 hi/lo operands
__device__ __align__(256) bf16  g_in_hi[BATCH * SEQ * DIM], g_in_lo[BATCH * SEQ * DIM];
__device__ __align__(256) bf16  g_pe_hi[SEQ * DIM],         g_pe_lo[SEQ * DIM];
__device__ __align__(256) bf16  g_WT_hi[4 * DIM * DIM],     g_WT_lo[4 * DIM * DIM];
__device__ __align__(256) bf16  g_q_hi[BATCH * SEQ * DIM],  g_q_lo[BATCH * SEQ * DIM];
__device__ __align__(256) bf16  g_k_hi[BATCH * SEQ * DIM],  g_k_lo[BATCH * SEQ * DIM];
__device__ __align__(256) bf16  g_vT_hi[BATCH * DIM * SEQ], g_vT_lo[BATCH * DIM * SEQ];
__device__ __align__(256) bf16  g_rk_hi[SEQ * DIM],         g_rk_lo[SEQ * DIM];
__device__ __align__(256) bf16  g_P_hi[(size_t)BATCH * SEQ * SEQ];
__device__ __align__(256) bf16  g_P_lo[(size_t)BATCH * SEQ * SEQ];

// ---------------- MMA helpers (validated) ----------------
__device__ __forceinline__ uint32_t smem_u32(const void* p) {
    uint32_t a;
    asm("{ .reg .u64 t; cvta.to.shared.u64 t, %1; cvt.u32.u64 %0, t; }" : "=r"(a) : "l"(p));
    return a;
}
__device__ __forceinline__ void ldsm4(uint32_t* r, uint32_t addr) {
    asm volatile("ldmatrix.sync.aligned.m8n8.x4.shared.b16 {%0,%1,%2,%3}, [%4];"
        : "=r"(r[0]), "=r"(r[1]), "=r"(r[2]), "=r"(r[3]) : "r"(addr));
}
__device__ __forceinline__ void mma16816(float* d, const uint32_t* a, uint32_t b0, uint32_t b1) {
    asm volatile("mma.sync.aligned.m16n8k16.row.col.f32.bf16.bf16.f32 "
        "{%0,%1,%2,%3}, {%4,%5,%6,%7}, {%8,%9}, {%0,%1,%2,%3};"
        : "+f"(d[0]), "+f"(d[1]), "+f"(d[2]), "+f"(d[3])
        : "r"(a[0]), "r"(a[1]), "r"(a[2]), "r"(a[3]), "r"(b0), "r"(b1));
}
#define TSTRIDE 144
#define TBYTES  (64 * TSTRIDE)

// ---------------- sinusoidal PE ----------------
__global__ void pe_kernel() {
    int idx = blockIdx.x * blockDim.x + threadIdx.x;
    if (idx >= SEQ * (DIM / 2)) return;
    int u = idx / (DIM / 2);
    int j = idx % (DIM / 2);
    const double sf = -9.210340371976184 / 255.0;
    double dt  = exp((double)j * sf);
    double s, c;
    sincos((double)u * dt, &s, &c);
    g_pe[u * DIM + j]           = (float)s;
    g_pe[u * DIM + DIM / 2 + j] = (float)c;
}

// ---------------- split inputs / pe to bf16 hi/lo ----------------
__global__ void splitin_kernel(const float* __restrict__ inputs) {
    int i = blockIdx.x * blockDim.x + threadIdx.x;
    const int nin = BATCH * SEQ * DIM;
    float x;
    bf16 *hi, *lo;
    if (i < nin) {
        x = inputs[i]; hi = &g_in_hi[i]; lo = &g_in_lo[i];
    } else if (i < nin + SEQ * DIM) {
        int j = i - nin;
        x = g_pe[j]; hi = &g_pe_hi[j]; lo = &g_pe_lo[j];
    } else return;
    bf16 h = __float2bfloat16(x);
    *hi = h;
    *lo = __float2bfloat16(x - __bfloat162float(h));
}

// ---------------- weight transpose + split ----------------
__global__ void wtrans_kernel(const float* __restrict__ W0, const float* __restrict__ W1,
                              const float* __restrict__ W2, const float* __restrict__ W3) {
    const float* W = (blockIdx.z == 0) ? W0 : (blockIdx.z == 1) ? W1
                   : (blockIdx.z == 2) ? W2 : W3;
    bf16* Oh = g_WT_hi + (size_t)blockIdx.z * DIM * DIM;
    bf16* Ol = g_WT_lo + (size_t)blockIdx.z * DIM * DIM;
    __shared__ float t[32][33];
    int tx = threadIdx.x, ty = threadIdx.y;
    int x0 = blockIdx.x * 32, y0 = blockIdx.y * 32;
#pragma unroll
    for (int k = 0; k < 4; k++)
        t[ty + k * 8][tx] = W[(size_t)(y0 + ty + k * 8) * DIM + x0 + tx];
    __syncthreads();
#pragma unroll
    for (int k = 0; k < 4; k++) {
        int n = x0 + ty + k * 8, d = y0 + tx;
        float x = t[tx][ty + k * 8];
        bf16 h = __float2bfloat16(x);
        Oh[(size_t)n * DIM + d] = h;
        Ol[(size_t)n * DIM + d] = __float2bfloat16(x - __bfloat162float(h));
    }
}

// ---------------- MMA projection GEMM: 128 thr, 4 warps, warp tile 32x32 ----------------
__global__ __launch_bounds__(128, 2) void gemm_proj() {
    int csel = blockIdx.z;
    if (csel == 3 && blockIdx.y >= 32) return;

    __shared__ __align__(16) char SM[4 * TBYTES];
    const int oAh = 0, oAl = TBYTES, oBh = 2 * TBYTES, oBl = 3 * TBYTES;
    uint32_t sm32 = smem_u32(SM);

    const bf16* Ahi = (csel == 3) ? g_pe_hi : g_in_hi;
    const bf16* Alo = (csel == 3) ? g_pe_lo : g_in_lo;
    const bf16* Bhi = g_WT_hi + (size_t)csel * DIM * DIM;
    const bf16* Blo = g_WT_lo + (size_t)csel * DIM * DIM;
    float* C  = (csel == 1) ? g_k : (csel == 3) ? g_rk : (float*)0;
    bf16* Chi = (csel == 0) ? g_q_hi : (csel == 1) ? g_k_hi : (csel == 3) ? g_rk_hi : (bf16*)0;
    bf16* Clo = (csel == 0) ? g_q_lo : (csel == 1) ? g_k_lo : (csel == 3) ? g_rk_lo : (bf16*)0;

    int tid = threadIdx.x, wid = tid >> 5, lane = tid & 31;
    int wm = wid >> 1, wn = wid & 1;
    int m0 = blockIdx.y * 64, n0 = blockIdx.x * 64;

    float4 pAh[4], pAl[4], pBh[4], pBl[4];
    auto fetch = [&](int c) {
        int k0 = c * 64;
#pragma unroll
        for (int t = 0; t < 4; t++) {
            int idx = tid + t * 128;
            int row = idx >> 3, seg = idx & 7;
            size_t ga = (size_t)(m0 + row) * DIM + k0 + seg * 8;
            size_t gb = (size_t)(n0 + row) * DIM + k0 + seg * 8;
            pAh[t] = *(const float4*)&Ahi[ga];
            pAl[t] = *(const float4*)&Alo[ga];
            pBh[t] = *(const float4*)&Bhi[gb];
            pBl[t] = *(const float4*)&Blo[gb];
        }
    };

    fetch(0);
    float acc[2][4][4] = {};
    for (int c = 0; c < 8; c++) {
        __syncthreads();
#pragma unroll
        for (int t = 0; t < 4; t++) {
            int idx = tid + t * 128;
            int row = idx >> 3, seg = idx & 7;
            int so = row * TSTRIDE + seg * 16;
            *(float4*)(SM + oAh + so) = pAh[t];
            *(float4*)(SM + oAl + so) = pAl[t];
            *(float4*)(SM + oBh + so) = pBh[t];
            *(float4*)(SM + oBl + so) = pBl[t];
        }
        __syncthreads();
        if (c < 7) fetch(c + 1);
#pragma unroll
        for (int k16 = 0; k16 < 4; k16++) {
            uint32_t kb = (uint32_t)(k16 * 32 + (lane >> 4) * 16);
            uint32_t ah[2][4], al[2][4], bh[2][4], bl[2][4];
#pragma unroll
            for (int f = 0; f < 2; f++) {
                uint32_t ro = (uint32_t)((wm * 32 + f * 16 + (lane & 15)) * TSTRIDE) + kb;
                ldsm4(ah[f], sm32 + oAh + ro);
                ldsm4(al[f], sm32 + oAl + ro);
            }
#pragma unroll
            for (int g = 0; g < 2; g++) {
                uint32_t ro = (uint32_t)((wn * 32 + g * 16 + (lane & 15)) * TSTRIDE) + kb;
                ldsm4(bh[g], sm32 + oBh + ro);
                ldsm4(bl[g], sm32 + oBl + ro);
            }
#pragma unroll
            for (int f = 0; f < 2; f++)
#pragma unroll
                for (int g = 0; g < 2; g++)
#pragma unroll
                    for (int sel = 0; sel < 2; sel++) {
                        int gi = g * 2 + sel;
                        mma16816(acc[f][gi], ah[f], bh[g][sel], bh[g][sel + 2]);
                        mma16816(acc[f][gi], ah[f], bl[g][sel], bl[g][sel + 2]);
                        mma16816(acc[f][gi], al[f], bh[g][sel], bh[g][sel + 2]);
                    }
        }
    }

#pragma unroll
    for (int f = 0; f < 2; f++)
#pragma unroll
        for (int g = 0; g < 2; g++)
#pragma unroll
            for (int sel = 0; sel < 2; sel++)
#pragma unroll
                for (int hh = 0; hh < 2; hh++) {
                    int gi = g * 2 + sel;
                    int row = m0 + wm * 32 + f * 16 + (lane >> 2) + hh * 8;
                    int col = n0 + wn * 32 + g * 16 + sel * 8 + (lane & 3) * 2;
                    float x0 = acc[f][gi][hh * 2], x1 = acc[f][gi][hh * 2 + 1];
                    bf16 h0 = __float2bfloat16(x0), h1 = __float2bfloat16(x1);
                    bf16 l0 = __float2bfloat16(x0 - __bfloat162float(h0));
                    bf16 l1 = __float2bfloat16(x1 - __bfloat162float(h1));
                    if (csel == 2) {
                        int b = row >> 11, j = row & 2047;
                        size_t o0 = (size_t)b * DIM * SEQ + (size_t)col * SEQ + j;
                        g_vT_hi[o0]       = h0;
                        g_vT_lo[o0]       = l0;
                        g_vT_hi[o0 + SEQ] = h1;
                        g_vT_lo[o0 + SEQ] = l1;
                    } else {
                        size_t o = (size_t)row * DIM + col;
                        if (C) *(float2*)&C[o] = make_float2(x0, x1);
                        Chi[o]     = h0;
                        Chi[o + 1] = h1;
                        Clo[o]     = l0;
                        Clo[o + 1] = l1;
                    }
                }
}

// ---------------- bias dot-vectors (proven) ----------------
__global__ void biasdot_kernel(const float* __restrict__ cb, const float* __restrict__ rb) {
    int gw   = (blockIdx.x * blockDim.x + threadIdx.x) >> 5;
    int lane = threadIdx.x & 31;
    const float* vecrow;
    const float* bias;
    float* dst;
    if (gw < BATCH * SEQ) {
        vecrow = g_k + (size_t)gw * DIM; bias = cb; dst = &g_ck[gw];
    } else if (gw < BATCH * SEQ + SEQ) {
        int u = gw - BATCH * SEQ;
        vecrow = g_rk + (size_t)u * DIM; bias = rb; dst = &g_rrel[u];
    } else return;
    float s = 0.f;
#pragma unroll
    for (int d = lane; d < DIM; d += 32) s += bias[d] * vecrow[d];
#pragma unroll
    for (int o = 16; o > 0; o >>= 1) s += __shfl_xor_sync(0xffffffffu, s, o);
    if (lane == 0) *dst = s;
}

// ---------------- MMA logits: unified N=192 (content 64 + band 128), K-chunks of 32 ----------------
// 256 thr, 8 warps (2m x 4n), warp tile 32m x 48n. All six operand tiles resident.
#define LSTRIDE 80
__global__ __launch_bounds__(256, 2) void logits_kernel() {
    __shared__ __align__(16) char SM[40960];
    const int oQh = 0, oQl = 5120, oKh = 10240, oKl = 15360, oBh = 20480, oBl = 30720;
    uint32_t sm32 = smem_u32(SM);
    __shared__ float ck_s[64];
    __shared__ float rrel_s[128];

    int tid = threadIdx.x, wid = tid >> 5, lane = tid & 31;
    int wm = wid >> 2, wn = wid & 3;
    int pair = blockIdx.x, bz = blockIdx.y;
    int ib = (int)((sqrtf(8.0f * (float)pair + 1.0f) - 1.0f) * 0.5f);
    while ((ib + 1) * (ib + 2) / 2 <= pair) ib++;
    while (ib * (ib + 1) / 2 > pair) ib--;
    int jb = pair - ib * (ib + 1) / 2;
    int i0 = ib * 64, j0 = jb * 64;
    int u0 = SEQ - 64 - i0 + j0;

    if (tid < 64) ck_s[tid] = g_ck[bz * SEQ + j0 + tid];
    if (tid < 128) {
        int u = u0 + tid;
        rrel_s[tid] = (u >= 0 && u < SEQ) ? g_rrel[u] : 0.f;
    }

    const bf16* qh = g_q_hi + (size_t)bz * SEQ * DIM;
    const bf16* ql = g_q_lo + (size_t)bz * SEQ * DIM;
    const bf16* kh = g_k_hi + (size_t)bz * SEQ * DIM;
    const bf16* kl = g_k_lo + (size_t)bz * SEQ * DIM;

    const float4 z4 = make_float4(0.f, 0.f, 0.f, 0.f);
    float acc[2][6][4] = {};

    for (int c = 0; c < 16; c++) {
        int k0 = c * 32;
        __syncthreads();
        {
            int row = tid >> 2, seg = tid & 3;
            int so = row * LSTRIDE + seg * 16;
            size_t gq = (size_t)(i0 + row) * DIM + k0 + seg * 8;
            *(float4*)(SM + oQh + so) = *(const float4*)&qh[gq];
            *(float4*)(SM + oQl + so) = *(const float4*)&ql[gq];
            size_t gk = (size_t)(j0 + row) * DIM + k0 + seg * 8;
            *(float4*)(SM + oKh + so) = *(const float4*)&kh[gk];
            *(float4*)(SM + oKl + so) = *(const float4*)&kl[gk];
#pragma unroll
            for (int t2 = 0; t2 < 2; t2++) {
                int idx = tid + t2 * 256;
                int br = idx >> 2, sg = idx & 3;
                int so2 = br * LSTRIDE + sg * 16;
                int u = u0 + br;
                if (u >= 0 && u < SEQ) {
                    size_t g = (size_t)u * DIM + k0 + sg * 8;
                    *(float4*)(SM + oBh + so2) = *(const float4*)&g_rk_hi[g];
                    *(float4*)(SM + oBl + so2) = *(const float4*)&g_rk_lo[g];
                } else {
                    *(float4*)(SM + oBh + so2) = z4;
                    *(float4*)(SM + oBl + so2) = z4;
                }
            }
        }
        __syncthreads();
#pragma unroll
        for (int k16 = 0; k16 < 2; k16++) {
            uint32_t kb = (uint32_t)(k16 * 32 + (lane >> 4) * 16);
            uint32_t ah[2][4], al[2][4], bh[3][4], bl[3][4];
#pragma unroll
            for (int f = 0; f < 2; f++) {
                uint32_t ro = (uint32_t)((wm * 32 + f * 16 + (lane & 15)) * LSTRIDE) + kb;
                ldsm4(ah[f], sm32 + oQh + ro);
                ldsm4(al[f], sm32 + oQl + ro);
            }
#pragma unroll
            for (int bf = 0; bf < 3; bf++) {
                int cb = wn * 48 + bf * 16;
                uint32_t roh, rol;
                if (cb < 64) {
                    uint32_t r = (uint32_t)((cb + (lane & 15)) * LSTRIDE) + kb;
                    roh = oKh + r; rol = oKl + r;
                } else {
                    uint32_t r = (uint32_t)((cb - 64 + (lane & 15)) * LSTRIDE) + kb;
                    roh = oBh + r; rol = oBl + r;
                }
                ldsm4(bh[bf], sm32 + roh);
                ldsm4(bl[bf], sm32 + rol);
            }
#pragma unroll
            for (int f = 0; f < 2; f++)
#pragma unroll
                for (int bf = 0; bf < 3; bf++)
#pragma unroll
                    for (int sel = 0; sel < 2; sel++) {
                        int gi = bf * 2 + sel;
                        mma16816(acc[f][gi], ah[f], bh[bf][sel], bh[bf][sel + 2]);
                        mma16816(acc[f][gi], ah[f], bl[bf][sel], bl[bf][sel + 2]);
                        mma16816(acc[f][gi], al[f], bh[bf][sel], bh[bf][sel + 2]);
                    }
        }
    }

    // stage band columns (>=64) into smem [64][130]; content stays in regs
    __syncthreads();
    float* bandS = (float*)SM;                   // 64*130*4 = 33280 <= 40960
#pragma unroll
    for (int f = 0; f < 2; f++)
#pragma unroll
        for (int bf = 0; bf < 3; bf++)
#pragma unroll
            for (int sel = 0; sel < 2; sel++)
#pragma unroll
                for (int hh = 0; hh < 2; hh++) {
                    int gi = bf * 2 + sel;
                    int col = wn * 48 + bf * 16 + sel * 8 + (lane & 3) * 2;
                    int row = wm * 32 + f * 16 + (lane >> 2) + hh * 8;
                    if (col >= 64)
                        *(float2*)&bandS[row * 130 + (col - 64)] =
                            make_float2(acc[f][gi][hh * 2], acc[f][gi][hh * 2 + 1]);
                }
    __syncthreads();

#pragma unroll
    for (int f = 0; f < 2; f++)
#pragma unroll
        for (int bf = 0; bf < 3; bf++)
#pragma unroll
            for (int sel = 0; sel < 2; sel++)
#pragma unroll
                for (int hh = 0; hh < 2; hh++) {
                    int gi = bf * 2 + sel;
                    int col = wn * 48 + bf * 16 + sel * 8 + (lane & 3) * 2;
                    if (col >= 64) continue;
                    int row = wm * 32 + f * 16 + (lane >> 2) + hh * 8;
                    int iig = i0 + row;
                    float o[2];
#pragma unroll
                    for (int e = 0; e < 2; e++) {
                        int jj = col + e;
                        if (j0 + jj > iig) {
                            o[e] = NEGBIG;
                        } else {
                            int t = jj - row + 63;
                            o[e] = SCALE * (acc[f][gi][hh * 2 + e] + ck_s[jj] +
                                            bandS[row * 130 + t] + rrel_s[t]);
                        }
                    }
                    *(float2*)&g_S[((size_t)(bz * SEQ + iig)) * SEQ + j0 + col] =
                        make_float2(o[0], o[1]);
                }
}

// ---------------- row softmax -> P hi/lo (2 rows per block, 128 thr/row) ----------------
__global__ __launch_bounds__(256) void softmax_kernel() {
    int sub = threadIdx.x >> 7;
    int t   = threadIdx.x & 127;
    int i   = blockIdx.x * 2 + sub;
    int bz  = blockIdx.y;
    int L   = ((i >> 6) + 1) << 6;
    size_t rowoff = ((size_t)(bz * SEQ + i)) * SEQ;
    const float* row = g_S + rowoff;
    int wid = threadIdx.x >> 5;

    float4 v4[4];
    int n = 0;
    float m = -3.4e38f;
    for (int j = t * 4; j < L; j += 512) {
        float4 x = *(const float4*)&row[j];
        v4[n++] = x;
        m = fmaxf(m, fmaxf(fmaxf(x.x, x.y), fmaxf(x.z, x.w)));
    }

    __shared__ float red[8];
#pragma unroll
    for (int o = 16; o > 0; o >>= 1) m = fmaxf(m, __shfl_xor_sync(0xffffffffu, m, o));
    if ((threadIdx.x & 31) == 0) red[wid] = m;
    __syncthreads();
    m = fmaxf(fmaxf(red[sub * 4 + 0], red[sub * 4 + 1]),
              fmaxf(red[sub * 4 + 2], red[sub * 4 + 3]));
    __syncthreads();

    float s = 0.f;
    for (int k2 = 0; k2 < n; k2++) {
        v4[k2].x = __expf(v4[k2].x - m);
        v4[k2].y = __expf(v4[k2].y - m);
        v4[k2].z = __expf(v4[k2].z - m);
        v4[k2].w = __expf(v4[k2].w - m);
        s += v4[k2].x + v4[k2].y + v4[k2].z + v4[k2].w;
    }
#pragma unroll
    for (int o = 16; o > 0; o >>= 1) s += __shfl_xor_sync(0xffffffffu, s, o);
    if ((threadIdx.x & 31) == 0) red[wid] = s;
    __syncthreads();
    float inv = 1.0f / (red[sub * 4 + 0] + red[sub * 4 + 1] +
                        red[sub * 4 + 2] + red[sub * 4 + 3]);

    n = 0;
    for (int j = t * 4; j < L; j += 512) {
        float4 p = v4[n++];
        p.x *= inv; p.y *= inv; p.z *= inv; p.w *= inv;
        float pv[4] = {p.x, p.y, p.z, p.w};
#pragma unroll
        for (int e = 0; e < 4; e++) {
            bf16 h = __float2bfloat16(pv[e]);
            g_P_hi[rowoff + j + e] = h;
            g_P_lo[rowoff + j + e] = __float2bfloat16(pv[e] - __bfloat162float(h));
        }
    }
}

// ---------------- MMA causal PV: 128 thr, 4 warps, warp tile 32x32 ----------------
__global__ __launch_bounds__(128, 2) void pv_kernel(float* __restrict__ out) {
    __shared__ __align__(16) char SM[4 * TBYTES];
    const int oAh = 0, oAl = TBYTES, oBh = 2 * TBYTES, oBl = 3 * TBYTES;
    uint32_t sm32 = smem_u32(SM);

    int tid = threadIdx.x, wid = tid >> 5, lane = tid & 31;
    int wm = wid >> 1, wn = wid & 1;
    int d0 = blockIdx.x * 64, ibk = blockIdx.y, bz = blockIdx.z;
    int i0 = ibk * 64;
    int nchunk = ibk + 1;

    const bf16* Ph = g_P_hi + (size_t)bz * SEQ * SEQ;
    const bf16* Pl = g_P_lo + (size_t)bz * SEQ * SEQ;
    const bf16* Vh = g_vT_hi + (size_t)bz * DIM * SEQ;
    const bf16* Vl = g_vT_lo + (size_t)bz * DIM * SEQ;

    float4 pAh[4], pAl[4], pBh[4], pBl[4];
    auto fetch = [&](int c) {
        int k0 = c * 64;
#pragma unroll
        for (int t = 0; t < 4; t++) {
            int idx = tid + t * 128;
            int row = idx >> 3, seg = idx & 7;
            size_t gp = (size_t)(i0 + row) * SEQ + k0 + seg * 8;
            size_t gv = (size_t)(d0 + row) * SEQ + k0 + seg * 8;
            pAh[t] = *(const float4*)&Ph[gp];
            pAl[t] = *(const float4*)&Pl[gp];
            pBh[t] = *(const float4*)&Vh[gv];
            pBl[t] = *(const float4*)&Vl[gv];
        }
    };

    fetch(0);
    float acc[2][4][4] = {};
    for (int c = 0; c < nchunk; c++) {
        __syncthreads();
#pragma unroll
        for (int t = 0; t < 4; t++) {
            int idx = tid + t * 128;
            int row = idx >> 3, seg = idx & 7;
            int so = row * TSTRIDE + seg * 16;
            *(float4*)(SM + oAh + so) = pAh[t];
            *(float4*)(SM + oAl + so) = pAl[t];
            *(float4*)(SM + oBh + so) = pBh[t];
            *(float4*)(SM + oBl + so) = pBl[t];
        }
        __syncthreads();
        if (c + 1 < nchunk) fetch(c + 1);
#pragma unroll
        for (int k16 = 0; k16 < 4; k16++) {
            uint32_t kb = (uint32_t)(k16 * 32 + (lane >> 4) * 16);
            uint32_t ah[2][4], al[2][4], bh[2][4], bl[2][4];
#pragma unroll
            for (int f = 0; f < 2; f++) {
                uint32_t ro = (uint32_t)((wm * 32 + f * 16 + (lane & 15)) * TSTRIDE) + kb;
                ldsm4(ah[f], sm32 + oAh + ro);
                ldsm4(al[f], sm32 + oAl + ro);
            }
#pragma unroll
            for (int g = 0; g < 2; g++) {
                uint32_t ro = (uint32_t)((wn * 32 + g * 16 + (lane & 15)) * TSTRIDE) + kb;
                ldsm4(bh[g], sm32 + oBh + ro);
                ldsm4(bl[g], sm32 + oBl + ro);
            }
#pragma unroll
            for (int f = 0; f < 2; f++)
#pragma unroll
                for (int g = 0; g < 2; g++)
#pragma unroll
                    for (int sel = 0; sel < 2; sel++) {
                        int gi = g * 2 + sel;
                        mma16816(acc[f][gi], ah[f], bh[g][sel], bh[g][sel + 2]);
                        mma16816(acc[f][gi], ah[f], bl[g][sel], bl[g][sel + 2]);
                        mma16816(acc[f][gi], al[f], bh[g][sel], bh[g][sel + 2]);
                    }
        }
    }

#pragma unroll
    for (int f = 0; f < 2; f++)
#pragma unroll
        for (int g = 0; g < 2; g++)
#pragma unroll
            for (int sel = 0; sel < 2; sel++)
#pragma unroll
                for (int hh = 0; hh < 2; hh++) {
                    int gi = g * 2 + sel;
                    int row = i0 + wm * 32 + f * 16 + (lane >> 2) + hh * 8;
                    int col = d0 + wn * 32 + g * 16 + sel * 8 + (lane & 3) * 2;
                    size_t o = (size_t)(bz * SEQ + row) * DIM + col;
                    *(float2*)&out[o] = make_float2(acc[f][gi][hh * 2], acc[f][gi][hh * 2 + 1]);
                }
}

// ---------------- launch ----------------
extern "C" void kernel_launch(void* const* d_in, const int* in_sizes, int n_in,
                              void* d_out, int out_size) {
    const float* inputs = (const float*)d_in[0];
    const float* Wq     = (const float*)d_in[1];
    const float* Wk     = (const float*)d_in[2];
    const float* Wv     = (const float*)d_in[3];
    const float* Wrel   = (const float*)d_in[4];
    const float* cb     = (const float*)d_in[5];
    const float* rb     = (const float*)d_in[6];
    float* out = (float*)d_out;

    pe_kernel<<<(SEQ * (DIM / 2) + 255) / 256, 256>>>();

    int nsplit = BATCH * SEQ * DIM + SEQ * DIM;
    splitin_kernel<<<(nsplit + 255) / 256, 256>>>(inputs);
    wtrans_kernel<<<dim3(16, 16, 4), dim3(32, 8)>>>(Wq, Wk, Wv, Wrel);

    gemm_proj<<<dim3(8, 256, 4), 128>>>();

    int warps = BATCH * SEQ + SEQ;
    biasdot_kernel<<<(warps * 32 + 255) / 256, 256>>>(cb, rb);

    logits_kernel<<<dim3(528, BATCH), 256>>>();
    softmax_kernel<<<dim3(SEQ / 2, BATCH), 256>>>();
    pv_kernel<<<dim3(8, 32, 8), 128>>>(out);
}

// round 16
// speedup vs baseline: 1.1319x; 1.1319x over previous
#include <cuda_runtime.h>
#include <cuda_bf16.h>
#include <math.h>
#include <stdint.h>

#define BATCH 8
#define SEQ   2048
#define DIM   512
#define SCALE 0.044194173824159216f   /* 1/sqrt(512) */
#define NEGBIG -1e30f

typedef __nv_bfloat16 bf16;

// ---------------- scratch (static device globals; no allocs) ----------------
__device__ __align__(256) float g_pe[SEQ * DIM];
__device__ __align__(256) float g_rk[SEQ * DIM];
__device__ __align__(256) float g_k [BATCH * SEQ * DIM];
__device__ __align__(256) float g_ck[BATCH * SEQ];
__device__ __align__(256) float g_rrel[SEQ];
__device__ __align__(256) float g_S[(size_t)BATCH * SEQ * SEQ];
// bf16 hi/lo operands
__device__ __align__(256) bf16  g_in_hi[BATCH * SEQ * DIM], g_in_lo[BATCH * SEQ * DIM];
__device__ __align__(256) bf16  g_pe_hi[SEQ * DIM],         g_pe_lo[SEQ * DIM];
__device__ __align__(256) bf16  g_WT_hi[4 * DIM * DIM],     g_WT_lo[4 * DIM * DIM];
__device__ __align__(256) bf16  g_q_hi[BATCH * SEQ * DIM],  g_q_lo[BATCH * SEQ * DIM];
__device__ __align__(256) bf16  g_k_hi[BATCH * SEQ * DIM],  g_k_lo[BATCH * SEQ * DIM];
__device__ __align__(256) bf16  g_vT_hi[BATCH * DIM * SEQ], g_vT_lo[BATCH * DIM * SEQ];
__device__ __align__(256) bf16  g_rk_hi[SEQ * DIM],         g_rk_lo[SEQ * DIM];
__device__ __align__(256) bf16  g_P_hi[(size_t)BATCH * SEQ * SEQ];
__device__ __align__(256) bf16  g_P_lo[(size_t)BATCH * SEQ * SEQ];

// ---------------- MMA helpers (validated) ----------------
__device__ __forceinline__ uint32_t smem_u32(const void* p) {
    uint32_t a;
    asm("{ .reg .u64 t; cvta.to.shared.u64 t, %1; cvt.u32.u64 %0, t; }" : "=r"(a) : "l"(p));
    return a;
}
__device__ __forceinline__ void ldsm4(uint32_t* r, uint32_t addr) {
    asm volatile("ldmatrix.sync.aligned.m8n8.x4.shared.b16 {%0,%1,%2,%3}, [%4];"
        : "=r"(r[0]), "=r"(r[1]), "=r"(r[2]), "=r"(r[3]) : "r"(addr));
}
__device__ __forceinline__ void mma16816(float* d, const uint32_t* a, uint32_t b0, uint32_t b1) {
    asm volatile("mma.sync.aligned.m16n8k16.row.col.f32.bf16.bf16.f32 "
        "{%0,%1,%2,%3}, {%4,%5,%6,%7}, {%8,%9}, {%0,%1,%2,%3};"
        : "+f"(d[0]), "+f"(d[1]), "+f"(d[2]), "+f"(d[3])
        : "r"(a[0]), "r"(a[1]), "r"(a[2]), "r"(a[3]), "r"(b0), "r"(b1));
}
#define TSTRIDE 144
#define TBYTES  (64 * TSTRIDE)

// ---------------- sinusoidal PE ----------------
__global__ void pe_kernel() {
    int idx = blockIdx.x * blockDim.x + threadIdx.x;
    if (idx >= SEQ * (DIM / 2)) return;
    int u = idx / (DIM / 2);
    int j = idx % (DIM / 2);
    const double sf = -9.210340371976184 / 255.0;
    double dt  = exp((double)j * sf);
    double s, c;
    sincos((double)u * dt, &s, &c);
    g_pe[u * DIM + j]           = (float)s;
    g_pe[u * DIM + DIM / 2 + j] = (float)c;
}

// ---------------- split inputs / pe to bf16 hi/lo ----------------
__global__ void splitin_kernel(const float* __restrict__ inputs) {
    int i = blockIdx.x * blockDim.x + threadIdx.x;
    const int nin = BATCH * SEQ * DIM;
    float x;
    bf16 *hi, *lo;
    if (i < nin) {
        x = inputs[i]; hi = &g_in_hi[i]; lo = &g_in_lo[i];
    } else if (i < nin + SEQ * DIM) {
        int j = i - nin;
        x = g_pe[j]; hi = &g_pe_hi[j]; lo = &g_pe_lo[j];
    } else return;
    bf16 h = __float2bfloat16(x);
    *hi = h;
    *lo = __float2bfloat16(x - __bfloat162float(h));
}

// ---------------- weight transpose + split ----------------
__global__ void wtrans_kernel(const float* __restrict__ W0, const float* __restrict__ W1,
                              const float* __restrict__ W2, const float* __restrict__ W3) {
    const float* W = (blockIdx.z == 0) ? W0 : (blockIdx.z == 1) ? W1
                   : (blockIdx.z == 2) ? W2 : W3;
    bf16* Oh = g_WT_hi + (size_t)blockIdx.z * DIM * DIM;
    bf16* Ol = g_WT_lo + (size_t)blockIdx.z * DIM * DIM;
    __shared__ float t[32][33];
    int tx = threadIdx.x, ty = threadIdx.y;
    int x0 = blockIdx.x * 32, y0 = blockIdx.y * 32;
#pragma unroll
    for (int k = 0; k < 4; k++)
        t[ty + k * 8][tx] = W[(size_t)(y0 + ty + k * 8) * DIM + x0 + tx];
    __syncthreads();
#pragma unroll
    for (int k = 0; k < 4; k++) {
        int n = x0 + ty + k * 8, d = y0 + tx;
        float x = t[tx][ty + k * 8];
        bf16 h = __float2bfloat16(x);
        Oh[(size_t)n * DIM + d] = h;
        Ol[(size_t)n * DIM + d] = __float2bfloat16(x - __bfloat162float(h));
    }
}

// ---------------- MMA projection GEMM: 128 thr, 4 warps, warp tile 32x32 ----------------
__global__ __launch_bounds__(128, 2) void gemm_proj() {
    int csel = blockIdx.z;
    if (csel == 3 && blockIdx.y >= 32) return;

    __shared__ __align__(16) char SM[4 * TBYTES];
    const int oAh = 0, oAl = TBYTES, oBh = 2 * TBYTES, oBl = 3 * TBYTES;
    uint32_t sm32 = smem_u32(SM);

    const bf16* Ahi = (csel == 3) ? g_pe_hi : g_in_hi;
    const bf16* Alo = (csel == 3) ? g_pe_lo : g_in_lo;
    const bf16* Bhi = g_WT_hi + (size_t)csel * DIM * DIM;
    const bf16* Blo = g_WT_lo + (size_t)csel * DIM * DIM;
    float* C  = (csel == 1) ? g_k : (csel == 3) ? g_rk : (float*)0;
    bf16* Chi = (csel == 0) ? g_q_hi : (csel == 1) ? g_k_hi : (csel == 3) ? g_rk_hi : (bf16*)0;
    bf16* Clo = (csel == 0) ? g_q_lo : (csel == 1) ? g_k_lo : (csel == 3) ? g_rk_lo : (bf16*)0;

    int tid = threadIdx.x, wid = tid >> 5, lane = tid & 31;
    int wm = wid >> 1, wn = wid & 1;
    int m0 = blockIdx.y * 64, n0 = blockIdx.x * 64;

    float4 pAh[4], pAl[4], pBh[4], pBl[4];
    auto fetch = [&](int c) {
        int k0 = c * 64;
#pragma unroll
        for (int t = 0; t < 4; t++) {
            int idx = tid + t * 128;
            int row = idx >> 3, seg = idx & 7;
            size_t ga = (size_t)(m0 + row) * DIM + k0 + seg * 8;
            size_t gb = (size_t)(n0 + row) * DIM + k0 + seg * 8;
            pAh[t] = *(const float4*)&Ahi[ga];
            pAl[t] = *(const float4*)&Alo[ga];
            pBh[t] = *(const float4*)&Bhi[gb];
            pBl[t] = *(const float4*)&Blo[gb];
        }
    };

    fetch(0);
    float acc[2][4][4] = {};
    for (int c = 0; c < 8; c++) {
        __syncthreads();
#pragma unroll
        for (int t = 0; t < 4; t++) {
            int idx = tid + t * 128;
            int row = idx >> 3, seg = idx & 7;
            int so = row * TSTRIDE + seg * 16;
            *(float4*)(SM + oAh + so) = pAh[t];
            *(float4*)(SM + oAl + so) = pAl[t];
            *(float4*)(SM + oBh + so) = pBh[t];
            *(float4*)(SM + oBl + so) = pBl[t];
        }
        __syncthreads();
        if (c < 7) fetch(c + 1);
#pragma unroll
        for (int k16 = 0; k16 < 4; k16++) {
            uint32_t kb = (uint32_t)(k16 * 32 + (lane >> 4) * 16);
            uint32_t ah[2][4], al[2][4], bh[2][4], bl[2][4];
#pragma unroll
            for (int f = 0; f < 2; f++) {
                uint32_t ro = (uint32_t)((wm * 32 + f * 16 + (lane & 15)) * TSTRIDE) + kb;
                ldsm4(ah[f], sm32 + oAh + ro);
                ldsm4(al[f], sm32 + oAl + ro);
            }
#pragma unroll
            for (int g = 0; g < 2; g++) {
                uint32_t ro = (uint32_t)((wn * 32 + g * 16 + (lane & 15)) * TSTRIDE) + kb;
                ldsm4(bh[g], sm32 + oBh + ro);
                ldsm4(bl[g], sm32 + oBl + ro);
            }
#pragma unroll
            for (int f = 0; f < 2; f++)
#pragma unroll
                for (int g = 0; g < 2; g++)
#pragma unroll
                    for (int sel = 0; sel < 2; sel++) {
                        int gi = g * 2 + sel;
                        mma16816(acc[f][gi], ah[f], bh[g][sel], bh[g][sel + 2]);
                        mma16816(acc[f][gi], ah[f], bl[g][sel], bl[g][sel + 2]);
                        mma16816(acc[f][gi], al[f], bh[g][sel], bh[g][sel + 2]);
                    }
        }
    }

#pragma unroll
    for (int f = 0; f < 2; f++)
#pragma unroll
        for (int g = 0; g < 2; g++)
#pragma unroll
            for (int sel = 0; sel < 2; sel++)
#pragma unroll
                for (int hh = 0; hh < 2; hh++) {
                    int gi = g * 2 + sel;
                    int row = m0 + wm * 32 + f * 16 + (lane >> 2) + hh * 8;
                    int col = n0 + wn * 32 + g * 16 + sel * 8 + (lane & 3) * 2;
                    float x0 = acc[f][gi][hh * 2], x1 = acc[f][gi][hh * 2 + 1];
                    bf16 h0 = __float2bfloat16(x0), h1 = __float2bfloat16(x1);
                    bf16 l0 = __float2bfloat16(x0 - __bfloat162float(h0));
                    bf16 l1 = __float2bfloat16(x1 - __bfloat162float(h1));
                    if (csel == 2) {
                        int b = row >> 11, j = row & 2047;
                        size_t o0 = (size_t)b * DIM * SEQ + (size_t)col * SEQ + j;
                        g_vT_hi[o0]       = h0;
                        g_vT_lo[o0]       = l0;
                        g_vT_hi[o0 + SEQ] = h1;
                        g_vT_lo[o0 + SEQ] = l1;
                    } else {
                        size_t o = (size_t)row * DIM + col;
                        if (C) *(float2*)&C[o] = make_float2(x0, x1);
                        Chi[o]     = h0;
                        Chi[o + 1] = h1;
                        Clo[o]     = l0;
                        Clo[o + 1] = l1;
                    }
                }
}

// ---------------- bias dot-vectors (proven) ----------------
__global__ void biasdot_kernel(const float* __restrict__ cb, const float* __restrict__ rb) {
    int gw   = (blockIdx.x * blockDim.x + threadIdx.x) >> 5;
    int lane = threadIdx.x & 31;
    const float* vecrow;
    const float* bias;
    float* dst;
    if (gw < BATCH * SEQ) {
        vecrow = g_k + (size_t)gw * DIM; bias = cb; dst = &g_ck[gw];
    } else if (gw < BATCH * SEQ + SEQ) {
        int u = gw - BATCH * SEQ;
        vecrow = g_rk + (size_t)u * DIM; bias = rb; dst = &g_rrel[u];
    } else return;
    float s = 0.f;
#pragma unroll
    for (int d = lane; d < DIM; d += 32) s += bias[d] * vecrow[d];
#pragma unroll
    for (int o = 16; o > 0; o >>= 1) s += __shfl_xor_sync(0xffffffffu, s, o);
    if (lane == 0) *dst = s;
}

// ---------------- MMA logits (validated R12 engine + Q register prefetch) ----------------
__global__ __launch_bounds__(256) void logits_kernel() {
    __shared__ __align__(16) char SM[4 * TBYTES];
    const int oQh = 0, oQl = TBYTES, oBh = 2 * TBYTES, oBl = 3 * TBYTES;
    uint32_t sm32 = smem_u32(SM);
    __shared__ float ck_s[64];
    __shared__ float rrel_s[128];

    int tid = threadIdx.x, wid = tid >> 5, lane = tid & 31;
    int wm = wid >> 2, wn = wid & 3;
    int pair = blockIdx.x, bz = blockIdx.y;
    int ib = (int)((sqrtf(8.0f * (float)pair + 1.0f) - 1.0f) * 0.5f);
    while ((ib + 1) * (ib + 2) / 2 <= pair) ib++;
    while (ib * (ib + 1) / 2 > pair) ib--;
    int jb = pair - ib * (ib + 1) / 2;
    int i0 = ib * 64, j0 = jb * 64;
    int u0 = SEQ - 64 - i0 + j0;

    if (tid < 64) ck_s[tid] = g_ck[bz * SEQ + j0 + tid];
    if (tid < 128) {
        int u = u0 + tid;
        rrel_s[tid] = (u >= 0 && u < SEQ) ? g_rrel[u] : 0.f;
    }

    const bf16* qh = g_q_hi + (size_t)bz * SEQ * DIM;
    const bf16* ql = g_q_lo + (size_t)bz * SEQ * DIM;
    const bf16* kh = g_k_hi + (size_t)bz * SEQ * DIM;
    const bf16* kl = g_k_lo + (size_t)bz * SEQ * DIM;

    const float4 z4 = make_float4(0.f, 0.f, 0.f, 0.f);
    float4 pBh4[2], pBl4[2];
    float4 pQh4[2], pQl4[2];
    auto fetchB = [&](int kind, int c) {
        int k0 = c * 64;
#pragma unroll
        for (int t = 0; t < 2; t++) {
            int idx = tid + t * 256;
            int row = idx >> 3, seg = idx & 7;
            if (kind == 0) {
                size_t g = (size_t)(j0 + row) * DIM + k0 + seg * 8;
                pBh4[t] = *(const float4*)&kh[g];
                pBl4[t] = *(const float4*)&kl[g];
            } else {
                int u = u0 + (kind - 1) * 64 + row;
                if (u >= 0 && u < SEQ) {
                    size_t g = (size_t)u * DIM + k0 + seg * 8;
                    pBh4[t] = *(const float4*)&g_rk_hi[g];
                    pBl4[t] = *(const float4*)&g_rk_lo[g];
                } else {
                    pBh4[t] = z4;
                    pBl4[t] = z4;
                }
            }
        }
    };
    auto fetchQ = [&](int c) {
        int k0 = c * 64;
#pragma unroll
        for (int t = 0; t < 2; t++) {
            int idx = tid + t * 256;
            int row = idx >> 3, seg = idx & 7;
            size_t g = (size_t)(i0 + row) * DIM + k0 + seg * 8;
            pQh4[t] = *(const float4*)&qh[g];
            pQl4[t] = *(const float4*)&ql[g];
        }
    };

    float accC[2][2][4] = {};
    float accB[2][2][2][4] = {};

    fetchB(0, 0);
    fetchQ(0);
    for (int c = 0; c < 8; c++) {
        __syncthreads();
#pragma unroll
        for (int t = 0; t < 2; t++) {
            int idx = tid + t * 256;
            int row = idx >> 3, seg = idx & 7;
            int so = row * TSTRIDE + seg * 16;
            *(float4*)(SM + oQh + so) = pQh4[t];
            *(float4*)(SM + oQl + so) = pQl4[t];
            *(float4*)(SM + oBh + so) = pBh4[t];
            *(float4*)(SM + oBl + so) = pBl4[t];
        }
        __syncthreads();
        fetchB(1, c);
#pragma unroll
        for (int k16 = 0; k16 < 4; k16++) {
            uint32_t kb = (uint32_t)(k16 * 32 + (lane >> 4) * 16);
            uint32_t ah[2][4], al[2][4], bh[4], bl[4];
#pragma unroll
            for (int f = 0; f < 2; f++) {
                uint32_t ro = (uint32_t)((wm * 32 + f * 16 + (lane & 15)) * TSTRIDE) + kb;
                ldsm4(ah[f], sm32 + oQh + ro);
                ldsm4(al[f], sm32 + oQl + ro);
            }
            {
                uint32_t ro = (uint32_t)((wn * 16 + (lane & 15)) * TSTRIDE) + kb;
                ldsm4(bh, sm32 + oBh + ro);
                ldsm4(bl, sm32 + oBl + ro);
            }
#pragma unroll
            for (int f = 0; f < 2; f++)
#pragma unroll
                for (int g = 0; g < 2; g++) {
                    mma16816(accC[f][g], ah[f], bh[g], bh[g + 2]);
                    mma16816(accC[f][g], ah[f], bl[g], bl[g + 2]);
                    mma16816(accC[f][g], al[f], bh[g], bh[g + 2]);
                }
        }
#pragma unroll
        for (int h = 0; h < 2; h++) {
            __syncthreads();
#pragma unroll
            for (int t = 0; t < 2; t++) {
                int idx = tid + t * 256;
                int row = idx >> 3, seg = idx & 7;
                int so = row * TSTRIDE + seg * 16;
                *(float4*)(SM + oBh + so) = pBh4[t];
                *(float4*)(SM + oBl + so) = pBl4[t];
            }
            __syncthreads();
            if (h == 0) {
                fetchB(2, c);
            } else if (c < 7) {
                fetchB(0, c + 1);
                fetchQ(c + 1);
            }
#pragma unroll
            for (int k16 = 0; k16 < 4; k16++) {
                uint32_t kb = (uint32_t)(k16 * 32 + (lane >> 4) * 16);
                uint32_t ah[2][4], al[2][4], bh[4], bl[4];
#pragma unroll
                for (int f = 0; f < 2; f++) {
                    uint32_t ro = (uint32_t)((wm * 32 + f * 16 + (lane & 15)) * TSTRIDE) + kb;
                    ldsm4(ah[f], sm32 + oQh + ro);
                    ldsm4(al[f], sm32 + oQl + ro);
                }
                {
                    uint32_t ro = (uint32_t)((wn * 16 + (lane & 15)) * TSTRIDE) + kb;
                    ldsm4(bh, sm32 + oBh + ro);
                    ldsm4(bl, sm32 + oBl + ro);
                }
#pragma unroll
                for (int f = 0; f < 2; f++)
#pragma unroll
                    for (int g = 0; g < 2; g++) {
                        mma16816(accB[h][f][g], ah[f], bh[g], bh[g + 2]);
                        mma16816(accB[h][f][g], ah[f], bl[g], bl[g + 2]);
                        mma16816(accB[h][f][g], al[f], bh[g], bh[g + 2]);
                    }
            }
        }
    }

    __syncthreads();
    float* bandS = (float*)SM;
#pragma unroll
    for (int h = 0; h < 2; h++)
#pragma unroll
        for (int f = 0; f < 2; f++)
#pragma unroll
            for (int g = 0; g < 2; g++)
#pragma unroll
                for (int hh = 0; hh < 2; hh++) {
                    int row = wm * 32 + f * 16 + (lane >> 2) + hh * 8;
                    int t = h * 64 + wn * 16 + g * 8 + (lane & 3) * 2;
                    *(float2*)&bandS[row * 130 + t] =
                        make_float2(accB[h][f][g][hh * 2], accB[h][f][g][hh * 2 + 1]);
                }
    __syncthreads();

#pragma unroll
    for (int f = 0; f < 2; f++)
#pragma unroll
        for (int g = 0; g < 2; g++)
#pragma unroll
            for (int hh = 0; hh < 2; hh++) {
                int row = wm * 32 + f * 16 + (lane >> 2) + hh * 8;
                int col = wn * 16 + g * 8 + (lane & 3) * 2;
                int iig = i0 + row;
                float o[2];
#pragma unroll
                for (int e = 0; e < 2; e++) {
                    int jj = col + e;
                    if (j0 + jj > iig) {
                        o[e] = NEGBIG;
                    } else {
                        int t = jj - row + 63;
                        o[e] = SCALE * (accC[f][g][hh * 2 + e] + ck_s[jj] +
                                        bandS[row * 130 + t] + rrel_s[t]);
                    }
                }
                *(float2*)&g_S[((size_t)(bz * SEQ + iig)) * SEQ + j0 + col] =
                    make_float2(o[0], o[1]);
            }
}

// ---------------- row softmax -> P hi/lo (2 rows per block, 128 thr/row) ----------------
__global__ __launch_bounds__(256) void softmax_kernel() {
    int sub = threadIdx.x >> 7;
    int t   = threadIdx.x & 127;
    int i   = blockIdx.x * 2 + sub;
    int bz  = blockIdx.y;
    int L   = ((i >> 6) + 1) << 6;
    size_t rowoff = ((size_t)(bz * SEQ + i)) * SEQ;
    const float* row = g_S + rowoff;
    int wid = threadIdx.x >> 5;

    float4 v4[4];
    int n = 0;
    float m = -3.4e38f;
    for (int j = t * 4; j < L; j += 512) {
        float4 x = *(const float4*)&row[j];
        v4[n++] = x;
        m = fmaxf(m, fmaxf(fmaxf(x.x, x.y), fmaxf(x.z, x.w)));
    }

    __shared__ float red[8];
#pragma unroll
    for (int o = 16; o > 0; o >>= 1) m = fmaxf(m, __shfl_xor_sync(0xffffffffu, m, o));
    if ((threadIdx.x & 31) == 0) red[wid] = m;
    __syncthreads();
    m = fmaxf(fmaxf(red[sub * 4 + 0], red[sub * 4 + 1]),
              fmaxf(red[sub * 4 + 2], red[sub * 4 + 3]));
    __syncthreads();

    float s = 0.f;
    for (int k2 = 0; k2 < n; k2++) {
        v4[k2].x = __expf(v4[k2].x - m);
        v4[k2].y = __expf(v4[k2].y - m);
        v4[k2].z = __expf(v4[k2].z - m);
        v4[k2].w = __expf(v4[k2].w - m);
        s += v4[k2].x + v4[k2].y + v4[k2].z + v4[k2].w;
    }
#pragma unroll
    for (int o = 16; o > 0; o >>= 1) s += __shfl_xor_sync(0xffffffffu, s, o);
    if ((threadIdx.x & 31) == 0) red[wid] = s;
    __syncthreads();
    float inv = 1.0f / (red[sub * 4 + 0] + red[sub * 4 + 1] +
                        red[sub * 4 + 2] + red[sub * 4 + 3]);

    n = 0;
    for (int j = t * 4; j < L; j += 512) {
        float4 p = v4[n++];
        p.x *= inv; p.y *= inv; p.z *= inv; p.w *= inv;
        float pv[4] = {p.x, p.y, p.z, p.w};
#pragma unroll
        for (int e = 0; e < 4; e++) {
            bf16 h = __float2bfloat16(pv[e]);
            g_P_hi[rowoff + j + e] = h;
            g_P_lo[rowoff + j + e] = __float2bfloat16(pv[e] - __bfloat162float(h));
        }
    }
}

// ---------------- MMA causal PV: 128 thr, 4 warps, warp tile 32x32 ----------------
__global__ __launch_bounds__(128, 2) void pv_kernel(float* __restrict__ out) {
    __shared__ __align__(16) char SM[4 * TBYTES];
    const int oAh = 0, oAl = TBYTES, oBh = 2 * TBYTES, oBl = 3 * TBYTES;
    uint32_t sm32 = smem_u32(SM);

    int tid = threadIdx.x, wid = tid >> 5, lane = tid & 31;
    int wm = wid >> 1, wn = wid & 1;
    int d0 = blockIdx.x * 64, ibk = blockIdx.y, bz = blockIdx.z;
    int i0 = ibk * 64;
    int nchunk = ibk + 1;

    const bf16* Ph = g_P_hi + (size_t)bz * SEQ * SEQ;
    const bf16* Pl = g_P_lo + (size_t)bz * SEQ * SEQ;
    const bf16* Vh = g_vT_hi + (size_t)bz * DIM * SEQ;
    const bf16* Vl = g_vT_lo + (size_t)bz * DIM * SEQ;

    float4 pAh[4], pAl[4], pBh[4], pBl[4];
    auto fetch = [&](int c) {
        int k0 = c * 64;
#pragma unroll
        for (int t = 0; t < 4; t++) {
            int idx = tid + t * 128;
            int row = idx >> 3, seg = idx & 7;
            size_t gp = (size_t)(i0 + row) * SEQ + k0 + seg * 8;
            size_t gv = (size_t)(d0 + row) * SEQ + k0 + seg * 8;
            pAh[t] = *(const float4*)&Ph[gp];
            pAl[t] = *(const float4*)&Pl[gp];
            pBh[t] = *(const float4*)&Vh[gv];
            pBl[t] = *(const float4*)&Vl[gv];
        }
    };

    fetch(0);
    float acc[2][4][4] = {};
    for (int c = 0; c < nchunk; c++) {
        __syncthreads();
#pragma unroll
        for (int t = 0; t < 4; t++) {
            int idx = tid + t * 128;
            int row = idx >> 3, seg = idx & 7;
            int so = row * TSTRIDE + seg * 16;
            *(float4*)(SM + oAh + so) = pAh[t];
            *(float4*)(SM + oAl + so) = pAl[t];
            *(float4*)(SM + oBh + so) = pBh[t];
            *(float4*)(SM + oBl + so) = pBl[t];
        }
        __syncthreads();
        if (c + 1 < nchunk) fetch(c + 1);
#pragma unroll
        for (int k16 = 0; k16 < 4; k16++) {
            uint32_t kb = (uint32_t)(k16 * 32 + (lane >> 4) * 16);
            uint32_t ah[2][4], al[2][4], bh[2][4], bl[2][4];
#pragma unroll
            for (int f = 0; f < 2; f++) {
                uint32_t ro = (uint32_t)((wm * 32 + f * 16 + (lane & 15)) * TSTRIDE) + kb;
                ldsm4(ah[f], sm32 + oAh + ro);
                ldsm4(al[f], sm32 + oAl + ro);
            }
#pragma unroll
            for (int g = 0; g < 2; g++) {
                uint32_t ro = (uint32_t)((wn * 32 + g * 16 + (lane & 15)) * TSTRIDE) + kb;
                ldsm4(bh[g], sm32 + oBh + ro);
                ldsm4(bl[g], sm32 + oBl + ro);
            }
#pragma unroll
            for (int f = 0; f < 2; f++)
#pragma unroll
                for (int g = 0; g < 2; g++)
#pragma unroll
                    for (int sel = 0; sel < 2; sel++) {
                        int gi = g * 2 + sel;
                        mma16816(acc[f][gi], ah[f], bh[g][sel], bh[g][sel + 2]);
                        mma16816(acc[f][gi], ah[f], bl[g][sel], bl[g][sel + 2]);
                        mma16816(acc[f][gi], al[f], bh[g][sel], bh[g][sel + 2]);
                    }
        }
    }

#pragma unroll
    for (int f = 0; f < 2; f++)
#pragma unroll
        for (int g = 0; g < 2; g++)
#pragma unroll
            for (int sel = 0; sel < 2; sel++)
#pragma unroll
                for (int hh = 0; hh < 2; hh++) {
                    int gi = g * 2 + sel;
                    int row = i0 + wm * 32 + f * 16 + (lane >> 2) + hh * 8;
                    int col = d0 + wn * 32 + g * 16 + sel * 8 + (lane & 3) * 2;
                    size_t o = (size_t)(bz * SEQ + row) * DIM + col;
                    *(float2*)&out[o] = make_float2(acc[f][gi][hh * 2], acc[f][gi][hh * 2 + 1]);
                }
}

// ---------------- launch ----------------
extern "C" void kernel_launch(void* const* d_in, const int* in_sizes, int n_in,
                              void* d_out, int out_size) {
    const float* inputs = (const float*)d_in[0];
    const float* Wq     = (const float*)d_in[1];
    const float* Wk     = (const float*)d_in[2];
    const float* Wv     = (const float*)d_in[3];
    const float* Wrel   = (const float*)d_in[4];
    const float* cb     = (const float*)d_in[5];
    const float* rb     = (const float*)d_in[6];
    float* out = (float*)d_out;

    pe_kernel<<<(SEQ * (DIM / 2) + 255) / 256, 256>>>();

    int nsplit = BATCH * SEQ * DIM + SEQ * DIM;
    splitin_kernel<<<(nsplit + 255) / 256, 256>>>(inputs);
    wtrans_kernel<<<dim3(16, 16, 4), dim3(32, 8)>>>(Wq, Wk, Wv, Wrel);

    gemm_proj<<<dim3(8, 256, 4), 128>>>();

    int warps = BATCH * SEQ + SEQ;
    biasdot_kernel<<<(warps * 32 + 255) / 256, 256>>>(cb, rb);

    logits_kernel<<<dim3(528, BATCH), 256>>>();
    softmax_kernel<<<dim3(SEQ / 2, BATCH), 256>>>();
    pv_kernel<<<dim3(8, 32, 8), 128>>>(out);
}

// round 17
// speedup vs baseline: 1.1499x; 1.0159x over previous
#include <cuda_runtime.h>
#include <cuda_bf16.h>
#include <math.h>
#include <stdint.h>

#define BATCH 8
#define SEQ   2048
#define DIM   512
#define SCALE 0.044194173824159216f   /* 1/sqrt(512) */
#define NEGBIG -1e30f

typedef __nv_bfloat16 bf16;

// ---------------- scratch (static device globals; no allocs) ----------------
__device__ __align__(256) float g_pe[SEQ * DIM];
__device__ __align__(256) float g_ck[BATCH * SEQ];
__device__ __align__(256) float g_rrel[SEQ];
__device__ __align__(256) float g_S[(size_t)BATCH * SEQ * SEQ];
// bf16 hi/lo operands
__device__ __align__(256) bf16  g_in_hi[BATCH * SEQ * DIM], g_in_lo[BATCH * SEQ * DIM];
__device__ __align__(256) bf16  g_pe_hi[SEQ * DIM],         g_pe_lo[SEQ * DIM];
__device__ __align__(256) bf16  g_WT_hi[4 * DIM * DIM],     g_WT_lo[4 * DIM * DIM];
__device__ __align__(256) bf16  g_q_hi[BATCH * SEQ * DIM],  g_q_lo[BATCH * SEQ * DIM];
__device__ __align__(256) bf16  g_k_hi[BATCH * SEQ * DIM],  g_k_lo[BATCH * SEQ * DIM];
__device__ __align__(256) bf16  g_vT_hi[BATCH * DIM * SEQ], g_vT_lo[BATCH * DIM * SEQ];
__device__ __align__(256) bf16  g_rk_hi[SEQ * DIM],         g_rk_lo[SEQ * DIM];
__device__ __align__(256) bf16  g_P_hi[(size_t)BATCH * SEQ * SEQ];
__device__ __align__(256) bf16  g_P_lo[(size_t)BATCH * SEQ * SEQ];

// ---------------- MMA helpers (validated) ----------------
__device__ __forceinline__ uint32_t smem_u32(const void* p) {
    uint32_t a;
    asm("{ .reg .u64 t; cvta.to.shared.u64 t, %1; cvt.u32.u64 %0, t; }" : "=r"(a) : "l"(p));
    return a;
}
__device__ __forceinline__ void ldsm4(uint32_t* r, uint32_t addr) {
    asm volatile("ldmatrix.sync.aligned.m8n8.x4.shared.b16 {%0,%1,%2,%3}, [%4];"
        : "=r"(r[0]), "=r"(r[1]), "=r"(r[2]), "=r"(r[3]) : "r"(addr));
}
__device__ __forceinline__ void mma16816(float* d, const uint32_t* a, uint32_t b0, uint32_t b1) {
    asm volatile("mma.sync.aligned.m16n8k16.row.col.f32.bf16.bf16.f32 "
        "{%0,%1,%2,%3}, {%4,%5,%6,%7}, {%8,%9}, {%0,%1,%2,%3};"
        : "+f"(d[0]), "+f"(d[1]), "+f"(d[2]), "+f"(d[3])
        : "r"(a[0]), "r"(a[1]), "r"(a[2]), "r"(a[3]), "r"(b0), "r"(b1));
}
#define TSTRIDE 144
#define TBYTES  (64 * TSTRIDE)

// ---------------- sinusoidal PE ----------------
__global__ void pe_kernel() {
    int idx = blockIdx.x * blockDim.x + threadIdx.x;
    if (idx >= SEQ * (DIM / 2)) return;
    int u = idx / (DIM / 2);
    int j = idx % (DIM / 2);
    const double sf = -9.210340371976184 / 255.0;
    double dt  = exp((double)j * sf);
    double s, c;
    sincos((double)u * dt, &s, &c);
    g_pe[u * DIM + j]           = (float)s;
    g_pe[u * DIM + DIM / 2 + j] = (float)c;
}

// ---------------- split inputs / pe to bf16 hi/lo ----------------
__global__ void splitin_kernel(const float* __restrict__ inputs) {
    int i = blockIdx.x * blockDim.x + threadIdx.x;
    const int nin = BATCH * SEQ * DIM;
    float x;
    bf16 *hi, *lo;
    if (i < nin) {
        x = inputs[i]; hi = &g_in_hi[i]; lo = &g_in_lo[i];
    } else if (i < nin + SEQ * DIM) {
        int j = i - nin;
        x = g_pe[j]; hi = &g_pe_hi[j]; lo = &g_pe_lo[j];
    } else return;
    bf16 h = __float2bfloat16(x);
    *hi = h;
    *lo = __float2bfloat16(x - __bfloat162float(h));
}

// ---------------- weight transpose + split ----------------
__global__ void wtrans_kernel(const float* __restrict__ W0, const float* __restrict__ W1,
                              const float* __restrict__ W2, const float* __restrict__ W3) {
    const float* W = (blockIdx.z == 0) ? W0 : (blockIdx.z == 1) ? W1
                   : (blockIdx.z == 2) ? W2 : W3;
    bf16* Oh = g_WT_hi + (size_t)blockIdx.z * DIM * DIM;
    bf16* Ol = g_WT_lo + (size_t)blockIdx.z * DIM * DIM;
    __shared__ float t[32][33];
    int tx = threadIdx.x, ty = threadIdx.y;
    int x0 = blockIdx.x * 32, y0 = blockIdx.y * 32;
#pragma unroll
    for (int k = 0; k < 4; k++)
        t[ty + k * 8][tx] = W[(size_t)(y0 + ty + k * 8) * DIM + x0 + tx];
    __syncthreads();
#pragma unroll
    for (int k = 0; k < 4; k++) {
        int n = x0 + ty + k * 8, d = y0 + tx;
        float x = t[tx][ty + k * 8];
        bf16 h = __float2bfloat16(x);
        Oh[(size_t)n * DIM + d] = h;
        Ol[(size_t)n * DIM + d] = __float2bfloat16(x - __bfloat162float(h));
    }
}

// ---------------- MMA projection GEMM: 128 thr, 4 warps, warp tile 32x32, 3 CTAs/SM ----------------
__global__ __launch_bounds__(128, 3) void gemm_proj() {
    int csel = blockIdx.z;
    if (csel == 3 && blockIdx.y >= 32) return;

    __shared__ __align__(16) char SM[4 * TBYTES];
    const int oAh = 0, oAl = TBYTES, oBh = 2 * TBYTES, oBl = 3 * TBYTES;
    uint32_t sm32 = smem_u32(SM);

    const bf16* Ahi = (csel == 3) ? g_pe_hi : g_in_hi;
    const bf16* Alo = (csel == 3) ? g_pe_lo : g_in_lo;
    const bf16* Bhi = g_WT_hi + (size_t)csel * DIM * DIM;
    const bf16* Blo = g_WT_lo + (size_t)csel * DIM * DIM;
    bf16* Chi = (csel == 0) ? g_q_hi : (csel == 1) ? g_k_hi : (csel == 3) ? g_rk_hi : (bf16*)0;
    bf16* Clo = (csel == 0) ? g_q_lo : (csel == 1) ? g_k_lo : (csel == 3) ? g_rk_lo : (bf16*)0;

    int tid = threadIdx.x, wid = tid >> 5, lane = tid & 31;
    int wm = wid >> 1, wn = wid & 1;
    int m0 = blockIdx.y * 64, n0 = blockIdx.x * 64;

    float4 pAh[4], pAl[4], pBh[4], pBl[4];
    auto fetch = [&](int c) {
        int k0 = c * 64;
#pragma unroll
        for (int t = 0; t < 4; t++) {
            int idx = tid + t * 128;
            int row = idx >> 3, seg = idx & 7;
            size_t ga = (size_t)(m0 + row) * DIM + k0 + seg * 8;
            size_t gb = (size_t)(n0 + row) * DIM + k0 + seg * 8;
            pAh[t] = *(const float4*)&Ahi[ga];
            pAl[t] = *(const float4*)&Alo[ga];
            pBh[t] = *(const float4*)&Bhi[gb];
            pBl[t] = *(const float4*)&Blo[gb];
        }
    };

    fetch(0);
    float acc[2][4][4] = {};
    for (int c = 0; c < 8; c++) {
        __syncthreads();
#pragma unroll
        for (int t = 0; t < 4; t++) {
            int idx = tid + t * 128;
            int row = idx >> 3, seg = idx & 7;
            int so = row * TSTRIDE + seg * 16;
            *(float4*)(SM + oAh + so) = pAh[t];
            *(float4*)(SM + oAl + so) = pAl[t];
            *(float4*)(SM + oBh + so) = pBh[t];
            *(float4*)(SM + oBl + so) = pBl[t];
        }
        __syncthreads();
        if (c < 7) fetch(c + 1);
#pragma unroll
        for (int k16 = 0; k16 < 4; k16++) {
            uint32_t kb = (uint32_t)(k16 * 32 + (lane >> 4) * 16);
            uint32_t ah[2][4], al[2][4], bh[2][4], bl[2][4];
#pragma unroll
            for (int f = 0; f < 2; f++) {
                uint32_t ro = (uint32_t)((wm * 32 + f * 16 + (lane & 15)) * TSTRIDE) + kb;
                ldsm4(ah[f], sm32 + oAh + ro);
                ldsm4(al[f], sm32 + oAl + ro);
            }
#pragma unroll
            for (int g = 0; g < 2; g++) {
                uint32_t ro = (uint32_t)((wn * 32 + g * 16 + (lane & 15)) * TSTRIDE) + kb;
                ldsm4(bh[g], sm32 + oBh + ro);
                ldsm4(bl[g], sm32 + oBl + ro);
            }
#pragma unroll
            for (int f = 0; f < 2; f++)
#pragma unroll
                for (int g = 0; g < 2; g++)
#pragma unroll
                    for (int sel = 0; sel < 2; sel++) {
                        int gi = g * 2 + sel;
                        mma16816(acc[f][gi], ah[f], bh[g][sel], bh[g][sel + 2]);
                        mma16816(acc[f][gi], ah[f], bl[g][sel], bl[g][sel + 2]);
                        mma16816(acc[f][gi], al[f], bh[g][sel], bh[g][sel + 2]);
                    }
        }
    }

#pragma unroll
    for (int f = 0; f < 2; f++)
#pragma unroll
        for (int g = 0; g < 2; g++)
#pragma unroll
            for (int sel = 0; sel < 2; sel++)
#pragma unroll
                for (int hh = 0; hh < 2; hh++) {
                    int gi = g * 2 + sel;
                    int row = m0 + wm * 32 + f * 16 + (lane >> 2) + hh * 8;
                    int col = n0 + wn * 32 + g * 16 + sel * 8 + (lane & 3) * 2;
                    float x0 = acc[f][gi][hh * 2], x1 = acc[f][gi][hh * 2 + 1];
                    bf16 h0 = __float2bfloat16(x0), h1 = __float2bfloat16(x1);
                    bf16 l0 = __float2bfloat16(x0 - __bfloat162float(h0));
                    bf16 l1 = __float2bfloat16(x1 - __bfloat162float(h1));
                    if (csel == 2) {
                        int b = row >> 11, j = row & 2047;
                        size_t o0 = (size_t)b * DIM * SEQ + (size_t)col * SEQ + j;
                        g_vT_hi[o0]       = h0;
                        g_vT_lo[o0]       = l0;
                        g_vT_hi[o0 + SEQ] = h1;
                        g_vT_lo[o0 + SEQ] = l1;
                    } else {
                        size_t o = (size_t)row * DIM + col;
                        Chi[o]     = h0;
                        Chi[o + 1] = h1;
                        Clo[o]     = l0;
                        Clo[o + 1] = l1;
                    }
                }
}

// ---------------- bias dot-vectors (validated hi/lo form from R5-R8) ----------------
__global__ void biasdot_kernel(const float* __restrict__ cb, const float* __restrict__ rb) {
    int gw   = (blockIdx.x * blockDim.x + threadIdx.x) >> 5;
    int lane = threadIdx.x & 31;
    const bf16 *vh, *vl;
    const float* bias;
    float* dst;
    if (gw < BATCH * SEQ) {
        vh = g_k_hi + (size_t)gw * DIM; vl = g_k_lo + (size_t)gw * DIM;
        bias = cb; dst = &g_ck[gw];
    } else if (gw < BATCH * SEQ + SEQ) {
        int u = gw - BATCH * SEQ;
        vh = g_rk_hi + (size_t)u * DIM; vl = g_rk_lo + (size_t)u * DIM;
        bias = rb; dst = &g_rrel[u];
    } else return;
    float s = 0.f;
#pragma unroll
    for (int d = lane; d < DIM; d += 32)
        s += bias[d] * (__bfloat162float(vh[d]) + __bfloat162float(vl[d]));
#pragma unroll
    for (int o = 16; o > 0; o >>= 1) s += __shfl_xor_sync(0xffffffffu, s, o);
    if (lane == 0) *dst = s;
}

// ---------------- MMA logits (validated R12 engine + Q register prefetch) ----------------
__global__ __launch_bounds__(256) void logits_kernel() {
    __shared__ __align__(16) char SM[4 * TBYTES];
    const int oQh = 0, oQl = TBYTES, oBh = 2 * TBYTES, oBl = 3 * TBYTES;
    uint32_t sm32 = smem_u32(SM);
    __shared__ float ck_s[64];
    __shared__ float rrel_s[128];

    int tid = threadIdx.x, wid = tid >> 5, lane = tid & 31;
    int wm = wid >> 2, wn = wid & 3;
    int pair = blockIdx.x, bz = blockIdx.y;
    int ib = (int)((sqrtf(8.0f * (float)pair + 1.0f) - 1.0f) * 0.5f);
    while ((ib + 1) * (ib + 2) / 2 <= pair) ib++;
    while (ib * (ib + 1) / 2 > pair) ib--;
    int jb = pair - ib * (ib + 1) / 2;
    int i0 = ib * 64, j0 = jb * 64;
    int u0 = SEQ - 64 - i0 + j0;

    if (tid < 64) ck_s[tid] = g_ck[bz * SEQ + j0 + tid];
    if (tid < 128) {
        int u = u0 + tid;
        rrel_s[tid] = (u >= 0 && u < SEQ) ? g_rrel[u] : 0.f;
    }

    const bf16* qh = g_q_hi + (size_t)bz * SEQ * DIM;
    const bf16* ql = g_q_lo + (size_t)bz * SEQ * DIM;
    const bf16* kh = g_k_hi + (size_t)bz * SEQ * DIM;
    const bf16* kl = g_k_lo + (size_t)bz * SEQ * DIM;

    const float4 z4 = make_float4(0.f, 0.f, 0.f, 0.f);
    float4 pBh4[2], pBl4[2];
    float4 pQh4[2], pQl4[2];
    auto fetchB = [&](int kind, int c) {
        int k0 = c * 64;
#pragma unroll
        for (int t = 0; t < 2; t++) {
            int idx = tid + t * 256;
            int row = idx >> 3, seg = idx & 7;
            if (kind == 0) {
                size_t g = (size_t)(j0 + row) * DIM + k0 + seg * 8;
                pBh4[t] = *(const float4*)&kh[g];
                pBl4[t] = *(const float4*)&kl[g];
            } else {
                int u = u0 + (kind - 1) * 64 + row;
                if (u >= 0 && u < SEQ) {
                    size_t g = (size_t)u * DIM + k0 + seg * 8;
                    pBh4[t] = *(const float4*)&g_rk_hi[g];
                    pBl4[t] = *(const float4*)&g_rk_lo[g];
                } else {
                    pBh4[t] = z4;
                    pBl4[t] = z4;
                }
            }
        }
    };
    auto fetchQ = [&](int c) {
        int k0 = c * 64;
#pragma unroll
        for (int t = 0; t < 2; t++) {
            int idx = tid + t * 256;
            int row = idx >> 3, seg = idx & 7;
            size_t g = (size_t)(i0 + row) * DIM + k0 + seg * 8;
            pQh4[t] = *(const float4*)&qh[g];
            pQl4[t] = *(const float4*)&ql[g];
        }
    };

    float accC[2][2][4] = {};
    float accB[2][2][2][4] = {};

    fetchB(0, 0);
    fetchQ(0);
    for (int c = 0; c < 8; c++) {
        __syncthreads();
#pragma unroll
        for (int t = 0; t < 2; t++) {
            int idx = tid + t * 256;
            int row = idx >> 3, seg = idx & 7;
            int so = row * TSTRIDE + seg * 16;
            *(float4*)(SM + oQh + so) = pQh4[t];
            *(float4*)(SM + oQl + so) = pQl4[t];
            *(float4*)(SM + oBh + so) = pBh4[t];
            *(float4*)(SM + oBl + so) = pBl4[t];
        }
        __syncthreads();
        fetchB(1, c);
#pragma unroll
        for (int k16 = 0; k16 < 4; k16++) {
            uint32_t kb = (uint32_t)(k16 * 32 + (lane >> 4) * 16);
            uint32_t ah[2][4], al[2][4], bh[4], bl[4];
#pragma unroll
            for (int f = 0; f < 2; f++) {
                uint32_t ro = (uint32_t)((wm * 32 + f * 16 + (lane & 15)) * TSTRIDE) + kb;
                ldsm4(ah[f], sm32 + oQh + ro);
                ldsm4(al[f], sm32 + oQl + ro);
            }
            {
                uint32_t ro = (uint32_t)((wn * 16 + (lane & 15)) * TSTRIDE) + kb;
                ldsm4(bh, sm32 + oBh + ro);
                ldsm4(bl, sm32 + oBl + ro);
            }
#pragma unroll
            for (int f = 0; f < 2; f++)
#pragma unroll
                for (int g = 0; g < 2; g++) {
                    mma16816(accC[f][g], ah[f], bh[g], bh[g + 2]);
                    mma16816(accC[f][g], ah[f], bl[g], bl[g + 2]);
                    mma16816(accC[f][g], al[f], bh[g], bh[g + 2]);
                }
        }
#pragma unroll
        for (int h = 0; h < 2; h++) {
            __syncthreads();
#pragma unroll
            for (int t = 0; t < 2; t++) {
                int idx = tid + t * 256;
                int row = idx >> 3, seg = idx & 7;
                int so = row * TSTRIDE + seg * 16;
                *(float4*)(SM + oBh + so) = pBh4[t];
                *(float4*)(SM + oBl + so) = pBl4[t];
            }
            __syncthreads();
            if (h == 0) {
                fetchB(2, c);
            } else if (c < 7) {
                fetchB(0, c + 1);
                fetchQ(c + 1);
            }
#pragma unroll
            for (int k16 = 0; k16 < 4; k16++) {
                uint32_t kb = (uint32_t)(k16 * 32 + (lane >> 4) * 16);
                uint32_t ah[2][4], al[2][4], bh[4], bl[4];
#pragma unroll
                for (int f = 0; f < 2; f++) {
                    uint32_t ro = (uint32_t)((wm * 32 + f * 16 + (lane & 15)) * TSTRIDE) + kb;
                    ldsm4(ah[f], sm32 + oQh + ro);
                    ldsm4(al[f], sm32 + oQl + ro);
                }
                {
                    uint32_t ro = (uint32_t)((wn * 16 + (lane & 15)) * TSTRIDE) + kb;
                    ldsm4(bh, sm32 + oBh + ro);
                    ldsm4(bl, sm32 + oBl + ro);
                }
#pragma unroll
                for (int f = 0; f < 2; f++)
#pragma unroll
                    for (int g = 0; g < 2; g++) {
                        mma16816(accB[h][f][g], ah[f], bh[g], bh[g + 2]);
                        mma16816(accB[h][f][g], ah[f], bl[g], bl[g + 2]);
                        mma16816(accB[h][f][g], al[f], bh[g], bh[g + 2]);
                    }
            }
        }
    }

    __syncthreads();
    float* bandS = (float*)SM;
#pragma unroll
    for (int h = 0; h < 2; h++)
#pragma unroll
        for (int f = 0; f < 2; f++)
#pragma unroll
            for (int g = 0; g < 2; g++)
#pragma unroll
                for (int hh = 0; hh < 2; hh++) {
                    int row = wm * 32 + f * 16 + (lane >> 2) + hh * 8;
                    int t = h * 64 + wn * 16 + g * 8 + (lane & 3) * 2;
                    *(float2*)&bandS[row * 130 + t] =
                        make_float2(accB[h][f][g][hh * 2], accB[h][f][g][hh * 2 + 1]);
                }
    __syncthreads();

#pragma unroll
    for (int f = 0; f < 2; f++)
#pragma unroll
        for (int g = 0; g < 2; g++)
#pragma unroll
            for (int hh = 0; hh < 2; hh++) {
                int row = wm * 32 + f * 16 + (lane >> 2) + hh * 8;
                int col = wn * 16 + g * 8 + (lane & 3) * 2;
                int iig = i0 + row;
                float o[2];
#pragma unroll
                for (int e = 0; e < 2; e++) {
                    int jj = col + e;
                    if (j0 + jj > iig) {
                        o[e] = NEGBIG;
                    } else {
                        int t = jj - row + 63;
                        o[e] = SCALE * (accC[f][g][hh * 2 + e] + ck_s[jj] +
                                        bandS[row * 130 + t] + rrel_s[t]);
                    }
                }
                *(float2*)&g_S[((size_t)(bz * SEQ + iig)) * SEQ + j0 + col] =
                    make_float2(o[0], o[1]);
            }
}

// ---------------- row softmax -> P hi/lo (2 rows per block, 128 thr/row) ----------------
__global__ __launch_bounds__(256) void softmax_kernel() {
    int sub = threadIdx.x >> 7;
    int t   = threadIdx.x & 127;
    int i   = blockIdx.x * 2 + sub;
    int bz  = blockIdx.y;
    int L   = ((i >> 6) + 1) << 6;
    size_t rowoff = ((size_t)(bz * SEQ + i)) * SEQ;
    const float* row = g_S + rowoff;
    int wid = threadIdx.x >> 5;

    float4 v4[4];
    int n = 0;
    float m = -3.4e38f;
    for (int j = t * 4; j < L; j += 512) {
        float4 x = *(const float4*)&row[j];
        v4[n++] = x;
        m = fmaxf(m, fmaxf(fmaxf(x.x, x.y), fmaxf(x.z, x.w)));
    }

    __shared__ float red[8];
#pragma unroll
    for (int o = 16; o > 0; o >>= 1) m = fmaxf(m, __shfl_xor_sync(0xffffffffu, m, o));
    if ((threadIdx.x & 31) == 0) red[wid] = m;
    __syncthreads();
    m = fmaxf(fmaxf(red[sub * 4 + 0], red[sub * 4 + 1]),
              fmaxf(red[sub * 4 + 2], red[sub * 4 + 3]));
    __syncthreads();

    float s = 0.f;
    for (int k2 = 0; k2 < n; k2++) {
        v4[k2].x = __expf(v4[k2].x - m);
        v4[k2].y = __expf(v4[k2].y - m);
        v4[k2].z = __expf(v4[k2].z - m);
        v4[k2].w = __expf(v4[k2].w - m);
        s += v4[k2].x + v4[k2].y + v4[k2].z + v4[k2].w;
    }
#pragma unroll
    for (int o = 16; o > 0; o >>= 1) s += __shfl_xor_sync(0xffffffffu, s, o);
    if ((threadIdx.x & 31) == 0) red[wid] = s;
    __syncthreads();
    float inv = 1.0f / (red[sub * 4 + 0] + red[sub * 4 + 1] +
                        red[sub * 4 + 2] + red[sub * 4 + 3]);

    n = 0;
    for (int j = t * 4; j < L; j += 512) {
        float4 p = v4[n++];
        p.x *= inv; p.y *= inv; p.z *= inv; p.w *= inv;
        float pv[4] = {p.x, p.y, p.z, p.w};
#pragma unroll
        for (int e = 0; e < 4; e++) {
            bf16 h = __float2bfloat16(pv[e]);
            g_P_hi[rowoff + j + e] = h;
            g_P_lo[rowoff + j + e] = __float2bfloat16(pv[e] - __bfloat162float(h));
        }
    }
}

// ---------------- MMA causal PV: 128 thr, 4 warps, warp tile 32x32, 3 CTAs/SM ----------------
__global__ __launch_bounds__(128, 3) void pv_kernel(float* __restrict__ out) {
    __shared__ __align__(16) char SM[4 * TBYTES];
    const int oAh = 0, oAl = TBYTES, oBh = 2 * TBYTES, oBl = 3 * TBYTES;
    uint32_t sm32 = smem_u32(SM);

    int tid = threadIdx.x, wid = tid >> 5, lane = tid & 31;
    int wm = wid >> 1, wn = wid & 1;
    int d0 = blockIdx.x * 64, ibk = blockIdx.y, bz = blockIdx.z;
    int i0 = ibk * 64;
    int nchunk = ibk + 1;

    const bf16* Ph = g_P_hi + (size_t)bz * SEQ * SEQ;
    const bf16* Pl = g_P_lo + (size_t)bz * SEQ * SEQ;
    const bf16* Vh = g_vT_hi + (size_t)bz * DIM * SEQ;
    const bf16* Vl = g_vT_lo + (size_t)bz * DIM * SEQ;

    float4 pAh[4], pAl[4], pBh[4], pBl[4];
    auto fetch = [&](int c) {
        int k0 = c * 64;
#pragma unroll
        for (int t = 0; t < 4; t++) {
            int idx = tid + t * 128;
            int row = idx >> 3, seg = idx & 7;
            size_t gp = (size_t)(i0 + row) * SEQ + k0 + seg * 8;
            size_t gv = (size_t)(d0 + row) * SEQ + k0 + seg * 8;
            pAh[t] = *(const float4*)&Ph[gp];
            pAl[t] = *(const float4*)&Pl[gp];
            pBh[t] = *(const float4*)&Vh[gv];
            pBl[t] = *(const float4*)&Vl[gv];
        }
    };

    fetch(0);
    float acc[2][4][4] = {};
    for (int c = 0; c < nchunk; c++) {
        __syncthreads();
#pragma unroll
        for (int t = 0; t < 4; t++) {
            int idx = tid + t * 128;
            int row = idx >> 3, seg = idx & 7;
            int so = row * TSTRIDE + seg * 16;
            *(float4*)(SM + oAh + so) = pAh[t];
            *(float4*)(SM + oAl + so) = pAl[t];
            *(float4*)(SM + oBh + so) = pBh[t];
            *(float4*)(SM + oBl + so) = pBl[t];
        }
        __syncthreads();
        if (c + 1 < nchunk) fetch(c + 1);
#pragma unroll
        for (int k16 = 0; k16 < 4; k16++) {
            uint32_t kb = (uint32_t)(k16 * 32 + (lane >> 4) * 16);
            uint32_t ah[2][4], al[2][4], bh[2][4], bl[2][4];
#pragma unroll
            for (int f = 0; f < 2; f++) {
                uint32_t ro = (uint32_t)((wm * 32 + f * 16 + (lane & 15)) * TSTRIDE) + kb;
                ldsm4(ah[f], sm32 + oAh + ro);
                ldsm4(al[f], sm32 + oAl + ro);
            }
#pragma unroll
            for (int g = 0; g < 2; g++) {
                uint32_t ro = (uint32_t)((wn * 32 + g * 16 + (lane & 15)) * TSTRIDE) + kb;
                ldsm4(bh[g], sm32 + oBh + ro);
                ldsm4(bl[g], sm32 + oBl + ro);
            }
#pragma unroll
            for (int f = 0; f < 2; f++)
#pragma unroll
                for (int g = 0; g < 2; g++)
#pragma unroll
                    for (int sel = 0; sel < 2; sel++) {
                        int gi = g * 2 + sel;
                        mma16816(acc[f][gi], ah[f], bh[g][sel], bh[g][sel + 2]);
                        mma16816(acc[f][gi], ah[f], bl[g][sel], bl[g][sel + 2]);
                        mma16816(acc[f][gi], al[f], bh[g][sel], bh[g][sel + 2]);
                    }
        }
    }

#pragma unroll
    for (int f = 0; f < 2; f++)
#pragma unroll
        for (int g = 0; g < 2; g++)
#pragma unroll
            for (int sel = 0; sel < 2; sel++)
#pragma unroll
                for (int hh = 0; hh < 2; hh++) {
                    int gi = g * 2 + sel;
                    int row = i0 + wm * 32 + f * 16 + (lane >> 2) + hh * 8;
                    int col = d0 + wn * 32 + g * 16 + sel * 8 + (lane & 3) * 2;
                    size_t o = (size_t)(bz * SEQ + row) * DIM + col;
                    *(float2*)&out[o] = make_float2(acc[f][gi][hh * 2], acc[f][gi][hh * 2 + 1]);
                }
}

// ---------------- launch ----------------
extern "C" void kernel_launch(void* const* d_in, const int* in_sizes, int n_in,
                              void* d_out, int out_size) {
    const float* inputs = (const float*)d_in[0];
    const float* Wq     = (const float*)d_in[1];
    const float* Wk     = (const float*)d_in[2];
    const float* Wv     = (const float*)d_in[3];
    const float* Wrel   = (const float*)d_in[4];
    const float* cb     = (const float*)d_in[5];
    const float* rb     = (const float*)d_in[6];
    float* out = (float*)d_out;

    pe_kernel<<<(SEQ * (DIM / 2) + 255) / 256, 256>>>();

    int nsplit = BATCH * SEQ * DIM + SEQ * DIM;
    splitin_kernel<<<(nsplit + 255) / 256, 256>>>(inputs);
    wtrans_kernel<<<dim3(16, 16, 4), dim3(32, 8)>>>(Wq, Wk, Wv, Wrel);

    gemm_proj<<<dim3(8, 256, 4), 128>>>();

    int warps = BATCH * SEQ + SEQ;
    biasdot_kernel<<<(warps * 32 + 255) / 256, 256>>>(cb, rb);

    logits_kernel<<<dim3(528, BATCH), 256>>>();
    softmax_kernel<<<dim3(SEQ / 2, BATCH), 256>>>();
    pv_kernel<<<dim3(8, 32, 8), 128>>>(out);
}